// round 9
// baseline (speedup 1.0000x reference)
#include <cuda_runtime.h>
#include <cstdint>

// Problem constants.
#define NIN   64
#define NOUT  64
#define HH    192
#define WW    192
#define HO    190
#define WO    190
#define OG    8            // output channels per block
#define NG    (NOUT / OG)  // 8 groups
#define MAXK  2048
#define WCAP  160          // smem-staged weight entries (actual = 128)
#define TROWS 20           // output rows per block
#define TCOLS 96           // output cols per block (6 px per thread x 16 tx)
#define PROWS 22           // patch rows
#define PST   100          // patch row stride in floats (400B, 16B-aligned rows)
#define PBUF  (PROWS * PST)
#define TH    320

typedef unsigned long long ull;

__device__ int g_start[NG * 512 + 1];
__device__ ull g_cnt[NG * 64];            // per (og, in_ch): 8x8-bit ol counts
__device__ __align__(16) ull g_w[MAXK * 10];

__device__ __forceinline__ ull pk2(float lo, float hi) {
    ull r;
    asm("mov.b64 %0, {%1, %2};" : "=l"(r) : "f"(lo), "f"(hi));
    return r;
}
// {a.hi, b.lo} — shifted pair from two adjacent even pairs.
__device__ __forceinline__ ull shpair(ull a, ull b) {
    ull r;
    asm("{ .reg .f32 x,y,z,w;\n\t"
        "mov.b64 {x,y}, %1;\n\t"
        "mov.b64 {z,w}, %2;\n\t"
        "mov.b64 %0, {y,z}; }"
        : "=l"(r) : "l"(a), "l"(b));
    return r;
}
__device__ __forceinline__ ull fma2(ull a, ull b, ull c) {
    ull d;
    asm("fma.rn.f32x2 %0, %1, %2, %3;" : "=l"(d) : "l"(a), "l"(b), "l"(c));
    return d;
}
__device__ __forceinline__ void cpa16(uint32_t d, const void* s) {
    asm volatile("cp.async.ca.shared.global [%0], [%1], 16;" :: "r"(d), "l"(s));
}
__device__ __forceinline__ void cpcommit() { asm volatile("cp.async.commit_group;"); }
__device__ __forceinline__ void cpwait0()  { asm volatile("cp.async.wait_group 0;"); }

// ---------------------------------------------------------------------------
// Prep (known-correct): CSR over (og, in_ch, ol) bins, duplicated (w,w) f32x2
// weight pairs, plus packed per-(og,in_ch) ol-count u64s.
// ---------------------------------------------------------------------------
__global__ void prep_kernel(const float* __restrict__ w,
                            const int* __restrict__ cin,
                            const int* __restrict__ cout,
                            int K) {
    __shared__ int cnt[4096];
    __shared__ int part[1024];
    int t = threadIdx.x;

    for (int e = t; e < 4096; e += 1024) cnt[e] = 0;
    __syncthreads();

    for (int k = t; k < K; k += 1024) {
        int o = cout[k], i = cin[k];
        int bin = ((o >> 3) << 9) | (i << 3) | (o & 7);
        atomicAdd(&cnt[bin], 1);
    }
    __syncthreads();

    int c4[4];
    int s = 0;
#pragma unroll
    for (int q = 0; q < 4; q++) { c4[q] = cnt[t * 4 + q]; s += c4[q]; }
    part[t] = s;
    __syncthreads();
    for (int off = 1; off < 1024; off <<= 1) {
        int v = (t >= off) ? part[t - off] : 0;
        __syncthreads();
        part[t] += v;
        __syncthreads();
    }
    int run = part[t] - s;
#pragma unroll
    for (int q = 0; q < 4; q++) {
        int bin = t * 4 + q;
        int c = c4[q];
        cnt[bin] = run;
        g_start[bin] = run;
        run += c;
    }
    if (t == 1023) g_start[4096] = run;
    __syncthreads();

    for (int e = t; e < NG * 64; e += 1024) {
        ull v = 0;
#pragma unroll
        for (int q = 0; q < 8; q++) {
            int c = g_start[e * 8 + q + 1] - g_start[e * 8 + q];
            v |= (ull)(unsigned)(c & 255) << (8 * q);
        }
        g_cnt[e] = v;
    }

    for (int k = t; k < K; k += 1024) {
        int o = cout[k], i = cin[k];
        int bin = ((o >> 3) << 9) | (i << 3) | (o & 7);
        int slot = atomicAdd(&cnt[bin], 1);
        if (slot < MAXK) {
            ull* dst = &g_w[(size_t)slot * 10];
#pragma unroll
            for (int q = 0; q < 9; q++) {
                float wv = w[k * 9 + q];
                dst[q] = pk2(wv, wv);
            }
            dst[9] = 0;
        }
    }
}

// ---------------------------------------------------------------------------
// Inner body: 27 FMA2 per entry (3 pixel pairs), 3 chains interleaved.
// Pair p uses E[r][p], O[r][p], E[r][p+1].
// Taps: r0 -> q0.x q0.y q1.x | r1 -> q1.y q2.x q2.y | r2 -> q3.x q3.y w8.
// ---------------------------------------------------------------------------
#define CONV_INNER(WRPTR)                                                     \
    do {                                                                      \
        const ulonglong2* wr = (const ulonglong2*)(WRPTR);                    \
        ulonglong2 q0 = wr[0], q1 = wr[1], q2 = wr[2], q3 = wr[3];            \
        ull w8 = ((const ull*)wr)[8];                                         \
        acc[ol][0] = fma2(E[0][0], q0.x, acc[ol][0]);                         \
        acc[ol][1] = fma2(E[0][1], q0.x, acc[ol][1]);                         \
        acc[ol][2] = fma2(E[0][2], q0.x, acc[ol][2]);                         \
        acc[ol][0] = fma2(O[0][0], q0.y, acc[ol][0]);                         \
        acc[ol][1] = fma2(O[0][1], q0.y, acc[ol][1]);                         \
        acc[ol][2] = fma2(O[0][2], q0.y, acc[ol][2]);                         \
        acc[ol][0] = fma2(E[0][1], q1.x, acc[ol][0]);                         \
        acc[ol][1] = fma2(E[0][2], q1.x, acc[ol][1]);                         \
        acc[ol][2] = fma2(E[0][3], q1.x, acc[ol][2]);                         \
        acc[ol][0] = fma2(E[1][0], q1.y, acc[ol][0]);                         \
        acc[ol][1] = fma2(E[1][1], q1.y, acc[ol][1]);                         \
        acc[ol][2] = fma2(E[1][2], q1.y, acc[ol][2]);                         \
        acc[ol][0] = fma2(O[1][0], q2.x, acc[ol][0]);                         \
        acc[ol][1] = fma2(O[1][1], q2.x, acc[ol][1]);                         \
        acc[ol][2] = fma2(O[1][2], q2.x, acc[ol][2]);                         \
        acc[ol][0] = fma2(E[1][1], q2.y, acc[ol][0]);                         \
        acc[ol][1] = fma2(E[1][2], q2.y, acc[ol][1]);                         \
        acc[ol][2] = fma2(E[1][3], q2.y, acc[ol][2]);                         \
        acc[ol][0] = fma2(E[2][0], q3.x, acc[ol][0]);                         \
        acc[ol][1] = fma2(E[2][1], q3.x, acc[ol][1]);                         \
        acc[ol][2] = fma2(E[2][2], q3.x, acc[ol][2]);                         \
        acc[ol][0] = fma2(O[2][0], q3.y, acc[ol][0]);                         \
        acc[ol][1] = fma2(O[2][1], q3.y, acc[ol][1]);                         \
        acc[ol][2] = fma2(O[2][2], q3.y, acc[ol][2]);                         \
        acc[ol][0] = fma2(E[2][1], w8,   acc[ol][0]);                         \
        acc[ol][1] = fma2(E[2][2], w8,   acc[ol][1]);                         \
        acc[ol][2] = fma2(E[2][3], w8,   acc[ol][2]);                         \
    } while (0)

#define PREFETCH(ch, buf)                                                     \
    do {                                                                      \
        const float* xc = xb + (ch) * (HH * WW);                              \
        uint32_t sb = pbase + (buf) * (PBUF * 4);                             \
        cpa16(sb + sd0, xc + go0);                                            \
        if (has1) cpa16(sb + sd1, xc + go1);                                  \
    } while (0)

__global__ __launch_bounds__(TH, 2)
void conv_kernel(const float* __restrict__ x,
                 const float* __restrict__ bias,
                 float* __restrict__ out) {
    __shared__ __align__(16) float patch[2][PBUF];     // 17.6 KB
    __shared__ __align__(16) ull ws[WCAP * 10];        // 12.8 KB
    __shared__ ull cw[64];
    __shared__ unsigned umask[2];

    int bz = blockIdx.z;
    int b = bz >> 3, og = bz & 7;
    int h0 = blockIdx.y * TROWS;
    int w0  = blockIdx.x ? (WO - TCOLS) : 0;   // 0 or 94 (2-col overlap, benign)
    int w0a = w0 & ~3;                         // 16B-aligned patch origin
    int xoff = w0 - w0a;                       // 0 or 2
    int t = threadIdx.x, ty = t >> 4, tx = t & 15;

    // Stage packed counts; ballots for used channels (warps 0,1 whole).
    if (t < 64) {
        ull c = g_cnt[(og << 6) + t];
        cw[t] = c;
        unsigned mm = __ballot_sync(0xFFFFFFFFu, c != 0);
        if ((t & 31) == 0) umask[t >> 5] = mm;
    }

    int jb = g_start[og << 9];
    int nE = g_start[(og << 9) + 512] - jb;
    int nStage = nE < WCAP ? nE : WCAP;
    for (int e = t; e < nStage * 10; e += TH) ws[e] = g_w[(size_t)jb * 10 + e];

    ull acc[OG][3];
#pragma unroll
    for (int ol = 0; ol < OG; ol++) {
        float bv = bias[og * OG + ol];
        acc[ol][0] = pk2(bv, bv);
        acc[ol][1] = acc[ol][0];
        acc[ol][2] = acc[ol][0];
    }
    __syncthreads();

    ull mask = (ull)umask[0] | ((ull)umask[1] << 32);
    uint32_t pbase = (uint32_t)__cvta_generic_to_shared(&patch[0][0]);
    const float* xb = x + (size_t)b * NIN * HH * WW;

    // Hoisted loader addressing: 22 rows x 25 chunks of 16B = 550 slots over
    // 320 threads (threads t<230 take a second slot).
    int r0 = t / 25, c0 = (t - r0 * 25) * 4;
    int ih0 = h0 + r0; if (ih0 > HH - 1) ih0 = HH - 1;
    int go0 = ih0 * WW + w0a + c0;
    uint32_t sd0 = (uint32_t)(r0 * PST + c0) * 4;
    int s2 = t + TH;
    bool has1 = s2 < PROWS * 25;               // t < 230
    int r1 = s2 / 25, c1 = (s2 - r1 * 25) * 4;
    int ih1 = h0 + r1; if (ih1 > HH - 1) ih1 = HH - 1;
    int go1 = ih1 * WW + w0a + c1;
    uint32_t sd1 = (uint32_t)(r1 * PST + c1) * 4;
    int pboff = ty * PST + xoff + tx * 6;

    // Pipelined channel loop: prefetch next patch while computing current.
    {
        const ull* wp = (nE <= WCAP) ? ws : &g_w[(size_t)jb * 10];
        ull m = mask;
        int i = m ? (__ffsll((long long)m) - 1) : -1;
        m &= m - 1;
        if (i >= 0) PREFETCH(i, 0);
        cpcommit();
        int cur = 0;
        while (i >= 0) {
            int nx = m ? (__ffsll((long long)m) - 1) : -1;
            m &= m - 1;
            cpwait0();
            __syncthreads();
            if (nx >= 0) PREFETCH(nx, cur ^ 1);
            cpcommit();

            // E pairs: direct 8B-aligned LDS.64 results; O pairs: 3 shpair/row.
            const float* pb = &patch[cur][pboff];
            ull E[3][4], O[3][3];
#pragma unroll
            for (int r = 0; r < 3; r++) {
                const ull* rp = (const ull*)(pb + r * PST);
                E[r][0] = rp[0]; E[r][1] = rp[1];
                E[r][2] = rp[2]; E[r][3] = rp[3];
                O[r][0] = shpair(E[r][0], E[r][1]);
                O[r][1] = shpair(E[r][1], E[r][2]);
                O[r][2] = shpair(E[r][2], E[r][3]);
            }

            ull cnts = cw[i];
#pragma unroll
            for (int ol = 0; ol < OG; ol++) {
                int n = (int)(cnts & 255);
                cnts >>= 8;
                while (n--) { CONV_INNER(wp); wp += 10; }
            }
            cur ^= 1;
            i = nx;
        }
    }

    // Store: 3 full float2 per ol (all 8B aligned; no partial px in-tile).
    int h = h0 + ty;
    if (h < HO) {
        int wb = w0 + tx * 6;
        float* ob = out + (((size_t)(b * NOUT + og * OG)) * HO + h) * WO + wb;
#pragma unroll
        for (int ol = 0; ol < OG; ol++) {
            float2 v0, v1, v2;
            asm("mov.b64 {%0, %1}, %2;" : "=f"(v0.x), "=f"(v0.y) : "l"(acc[ol][0]));
            asm("mov.b64 {%0, %1}, %2;" : "=f"(v1.x), "=f"(v1.y) : "l"(acc[ol][1]));
            asm("mov.b64 {%0, %1}, %2;" : "=f"(v2.x), "=f"(v2.y) : "l"(acc[ol][2]));
            float* p = ob + (size_t)ol * HO * WO;
            *(float2*)p = v0;
            *(float2*)(p + 2) = v1;
            *(float2*)(p + 4) = v2;
        }
    }
}

// ---------------------------------------------------------------------------
extern "C" void kernel_launch(void* const* d_in, const int* in_sizes, int n_in,
                              void* d_out, int out_size) {
    const float* x    = (const float*)d_in[0];
    const float* w    = (const float*)d_in[1];
    const float* bias = (const float*)d_in[2];
    const int*   cin  = (const int*)d_in[3];
    const int*   cout = (const int*)d_in[4];
    int K = in_sizes[3];                       // 1024
    int B = in_sizes[0] / (NIN * HH * WW);     // 4

    prep_kernel<<<1, 1024>>>(w, cin, cout, K);

    dim3 grid(2, (HO + TROWS - 1) / TROWS, B * NG);   // (2, 10, 32)
    conv_kernel<<<grid, TH>>>(x, bias, (float*)d_out);
}

// round 13
// speedup vs baseline: 1.0992x; 1.0992x over previous
#include <cuda_runtime.h>
#include <cuda_bf16.h>
#include <cstdint>

#define HO 190
#define WO 190
#define XROW 8448                 // 66 cols x 128B per (slot,pass) row
#define XS_BYTES (4 * 2 * XROW)   // 67584
#define BF_OFF XS_BYTES
#define BF_BYTES 147456           // 36 ksteps x 16 ntiles x 32 lanes x 8B
#define DS_OFF (BF_OFF + BF_BYTES)
#define SMEM_TOTAL (DS_OFF + 64 * 68 * 4)   // 232448 = 227KB exactly

typedef unsigned long long ull;

__device__ float g_Wd[64 * 9 * 64];                     // [o][tap][i]
__device__ unsigned g_B[36 * 16 * 32 * 2];              // b-frags, reg order
__device__ __align__(16) __nv_bfloat16 g_xh[4ull * 192 * 192 * 64]; // [b][h][w][i]
__device__ __align__(16) __nv_bfloat16 g_xl[4ull * 192 * 192 * 64];

__device__ __forceinline__ void cpa16(uint32_t d, const void* s) {
    asm volatile("cp.async.ca.shared.global [%0], [%1], 16;" :: "r"(d), "l"(s));
}
#define CPCOMMIT() asm volatile("cp.async.commit_group;")
#define CPWAIT0()  asm volatile("cp.async.wait_group 0;")

// ------------------------- prep kernels -------------------------
__global__ void k_zero() {
    int i = blockIdx.x * 1024 + threadIdx.x;
    if (i < 64 * 9 * 64) g_Wd[i] = 0.0f;
}
__global__ void k_scatter(const float* __restrict__ w, const int* __restrict__ cin,
                          const int* __restrict__ cout, int K) {
    int k = blockIdx.x * 256 + threadIdx.x;
    if (k < K) {
        int o = cout[k], i = cin[k];
#pragma unroll
        for (int t = 0; t < 9; t++)
            atomicAdd(&g_Wd[(o * 9 + t) * 64 + i], w[k * 9 + t]);
    }
}
// B-frags for mma.m16n8k16 (B col-major frag: lane holds n = lane/4,
// k = kstep*16 + (lane%4)*2 (+1), reg1 at k+8). n<64 -> bf16-hi(W), n>=64 -> lo.
__global__ void k_buildB() {
    int idx = blockIdx.x * 256 + threadIdx.x;   // 36*16*32 = 18432
    if (idx >= 18432) return;
    int lane = idx & 31, nt = (idx >> 5) & 15, ks = idx >> 9;
    int n = nt * 8 + (lane >> 2);
    int o = n & 63;
    bool lo = n >= 64;
    int kk = ks * 16 + (lane & 3) * 2;
#pragma unroll
    for (int rr = 0; rr < 2; rr++) {
        unsigned pk = 0;
#pragma unroll
        for (int e = 0; e < 2; e++) {
            int k = kk + rr * 8 + e;
            int tap = k >> 6, i = k & 63;
            float v = g_Wd[(o * 9 + tap) * 64 + i];
            __nv_bfloat16 h = __float2bfloat16(v);
            __nv_bfloat16 val = lo ? __float2bfloat16(v - __bfloat162float(h)) : h;
            pk |= (unsigned)__bfloat16_as_ushort(val) << (16 * e);
        }
        g_B[idx * 2 + rr] = pk;
    }
}
// x -> channel-last bf16 hi/lo: g_xh/g_xl[b][h][w][i], 128B per (h,w).
__global__ void k_transpose(const float* __restrict__ x) {
    __shared__ float sm[64 * 192];
    int h = blockIdx.x, b = blockIdx.y, t = threadIdx.x;
    for (int idx = t; idx < 64 * 192; idx += 256) {
        int i = idx / 192, w = idx % 192;
        sm[idx] = x[(((size_t)b * 64 + i) * 192 + h) * 192 + w];
    }
    __syncthreads();
    if (t < 192) {
        unsigned hv[32], lv[32];
#pragma unroll
        for (int q = 0; q < 32; q++) {
            float f0 = sm[(2 * q) * 192 + t], f1 = sm[(2 * q + 1) * 192 + t];
            __nv_bfloat16 h0 = __float2bfloat16(f0), h1 = __float2bfloat16(f1);
            __nv_bfloat16 l0 = __float2bfloat16(f0 - __bfloat162float(h0));
            __nv_bfloat16 l1 = __float2bfloat16(f1 - __bfloat162float(h1));
            hv[q] = (unsigned)__bfloat16_as_ushort(h0) | ((unsigned)__bfloat16_as_ushort(h1) << 16);
            lv[q] = (unsigned)__bfloat16_as_ushort(l0) | ((unsigned)__bfloat16_as_ushort(l1) << 16);
        }
        size_t base = (((size_t)b * 192 + h) * 192 + t) * 32;   // u32 units
        uint4* dh = (uint4*)g_xh + base / 4;
        uint4* dl = (uint4*)g_xl + base / 4;
#pragma unroll
        for (int q = 0; q < 8; q++) {
            dh[q] = make_uint4(hv[4*q], hv[4*q+1], hv[4*q+2], hv[4*q+3]);
            dl[q] = make_uint4(lv[4*q], lv[4*q+1], lv[4*q+2], lv[4*q+3]);
        }
    }
}

// ------------------------- conv kernel -------------------------
// grid (3, 19, 4): x = w-strip {0,64,126}, y = 10-row h chunk, z = batch.
// 256 thr / 8 warps; warp tile m32 x n64 of GEMM M=128 (hi|lo px) N=128 (Wh|Wl).
__global__ __launch_bounds__(256, 1)
void conv_mma(const float* __restrict__ bias, float* __restrict__ out) {
    extern __shared__ __align__(16) char smem[];
    uint32_t sb = (uint32_t)__cvta_generic_to_shared(smem);
    int tid = threadIdx.x, lane = tid & 31, warp = tid >> 5;
    int wm = warp >> 1, wn = warp & 1;       // wm: m-strip 0..3, wn: n-half
    int pass = wm >> 1;                       // 0 = hi px, 1 = lo px
    int pbase = (wm & 1) * 32;                // pixel base within 64

    int b = blockIdx.z, h0 = blockIdx.y * 10;
    int w0 = (blockIdx.x == 0) ? 0 : (blockIdx.x == 1 ? 64 : 126);

    const __nv_bfloat16* xh = g_xh + (size_t)b * 192 * 192 * 64;
    const __nv_bfloat16* xl = g_xl + (size_t)b * 192 * 192 * 64;

    // Stage full B-frag table (144 KB) once.
    for (int cc = tid; cc < BF_BYTES / 16; cc += 256)
        cpa16(sb + BF_OFF + cc * 16, (const char*)g_B + cc * 16);

    // Stage one (h-row, both passes): 66 cols x 8 chunks, XOR-swizzled.
#define STAGE(hh) do {                                                         \
        int _s = (hh) & 3;                                                     \
        const __nv_bfloat16* s0 = xh + (((size_t)(hh)) * 192 + w0) * 64;       \
        const __nv_bfloat16* s1 = xl + (((size_t)(hh)) * 192 + w0) * 64;       \
        for (int cc = tid; cc < 528; cc += 256) {                              \
            int ws_ = cc >> 3, j = cc & 7;                                     \
            uint32_t dof = (uint32_t)(ws_ * 128 + ((j ^ (ws_ & 7)) * 16));     \
            cpa16(sb + (uint32_t)((_s * 2 + 0) * XROW) + dof,                  \
                  (const char*)s0 + ws_ * 128 + j * 16);                       \
            cpa16(sb + (uint32_t)((_s * 2 + 1) * XROW) + dof,                  \
                  (const char*)s1 + ws_ * 128 + j * 16);                       \
        } } while (0)

    STAGE(h0); STAGE(h0 + 1); STAGE(h0 + 2);
    CPCOMMIT();

    float* Ds = (float*)(smem + DS_OFF);     // [64 px][68] fp32

    for (int r = 0; r < 10; r++) {
        int h = h0 + r;
        CPWAIT0();
        __syncthreads();
        if (r < 9) STAGE(h + 3);             // overwrites slot (h-1)&3 (free)
        CPCOMMIT();

        float acc[2][8][4];
#pragma unroll
        for (int mt = 0; mt < 2; mt++)
#pragma unroll
            for (int nt = 0; nt < 8; nt++)
#pragma unroll
                for (int e = 0; e < 4; e++) acc[mt][nt][e] = 0.0f;

#pragma unroll
        for (int tap = 0; tap < 9; tap++) {
            const int dh = tap / 3, dw = tap % 3;
            int slot = (h + dh) & 3;
            uint32_t arow = sb + (uint32_t)((slot * 2 + pass) * XROW);
#pragma unroll
            for (int sub = 0; sub < 4; sub++) {
                int ks = tap * 4 + sub;
                // B frags for this warp's n-half (same for both m-tiles).
                unsigned bf[8][2];
#pragma unroll
                for (int nt = 0; nt < 8; nt++) {
                    uint2 bv = *(const uint2*)(smem + BF_OFF +
                        (((size_t)(ks * 16 + wn * 8 + nt) * 32 + lane) << 3));
                    bf[nt][0] = bv.x; bf[nt][1] = bv.y;
                }
                // A frags via ldmatrix.x4 (m16k16 each).
                unsigned af[2][4];
#pragma unroll
                for (int mt = 0; mt < 2; mt++) {
                    int px = pbase + mt * 16 + (lane & 15);
                    int wl = px + dw;
                    int kc = lane >> 4;
                    uint32_t ad = arow + (uint32_t)(wl * 128 +
                                  (((sub * 2 + kc) ^ (wl & 7)) * 16));
                    asm volatile(
                        "ldmatrix.sync.aligned.m8n8.x4.shared.b16 {%0,%1,%2,%3}, [%4];"
                        : "=r"(af[mt][0]), "=r"(af[mt][1]),
                          "=r"(af[mt][2]), "=r"(af[mt][3]) : "r"(ad));
                }
#pragma unroll
                for (int mt = 0; mt < 2; mt++)
#pragma unroll
                    for (int nt = 0; nt < 8; nt++)
                        asm volatile(
                            "mma.sync.aligned.m16n8k16.row.col.f32.bf16.bf16.f32 "
                            "{%0,%1,%2,%3}, {%4,%5,%6,%7}, {%8,%9}, {%0,%1,%2,%3};"
                            : "+f"(acc[mt][nt][0]), "+f"(acc[mt][nt][1]),
                              "+f"(acc[mt][nt][2]), "+f"(acc[mt][nt][3])
                            : "r"(af[mt][0]), "r"(af[mt][1]),
                              "r"(af[mt][2]), "r"(af[mt][3]),
                              "r"(bf[nt][0]), "r"(bf[nt][1]));
            }
        }

        // Epilogue: y = D[hi,Wh] + D[hi,Wl] + D[lo,Wh] via Dstage.
        // Common frag coords: px = pbase + mt*16 + lane/4 (+8), o = nt*8 + (lane%4)*2.
#define FRAG_LOOP(...)                                                         \
        _Pragma("unroll")                                                      \
        for (int mt = 0; mt < 2; mt++) {                                       \
            int r0 = pbase + mt * 16 + (lane >> 2);                            \
            _Pragma("unroll")                                                  \
            for (int nt = 0; nt < 8; nt++) {                                   \
                int c = nt * 8 + (lane & 3) * 2;                               \
                float2* p0 = (float2*)&Ds[r0 * 68 + c];                        \
                float2* p1 = (float2*)&Ds[(r0 + 8) * 68 + c];                  \
                __VA_ARGS__;                                                   \
            }                                                                  \
        }
        if (wm < 2 && wn == 0)   // hi px * Wh : store
            FRAG_LOOP(*p0 = make_float2(acc[mt][nt][0], acc[mt][nt][1]);
                      *p1 = make_float2(acc[mt][nt][2], acc[mt][nt][3]));
        __syncthreads();
        if (wm < 2 && wn == 1)   // hi px * Wl : add
            FRAG_LOOP(float2 v0 = *p0;
                      float2 v1 = *p1;
                      v0.x += acc[mt][nt][0]; v0.y += acc[mt][nt][1];
                      v1.x += acc[mt][nt][2]; v1.y += acc[mt][nt][3];
                      *p0 = v0; *p1 = v1);
        __syncthreads();
        if (wm >= 2 && wn == 0)  // lo px * Wh : add
            FRAG_LOOP(float2 v0 = *p0;
                      float2 v1 = *p1;
                      v0.x += acc[mt][nt][0]; v0.y += acc[mt][nt][1];
                      v1.x += acc[mt][nt][2]; v1.y += acc[mt][nt][3];
                      *p0 = v0; *p1 = v1);
        __syncthreads();

        // Store: thread t -> o = t/4, px chunk (t%4)*16, 8 float2 per thread.
        {
            int o = tid >> 2, px0 = (tid & 3) * 16;
            float bv = bias[o];
            float* op = out + (((size_t)(b * 64 + o)) * HO + h) * WO + w0 + px0;
#pragma unroll
            for (int q = 0; q < 16; q += 2) {
                float2 v;
                v.x = Ds[(px0 + q) * 68 + o] + bv;
                v.y = Ds[(px0 + q + 1) * 68 + o] + bv;
                *(float2*)(op + q) = v;
            }
        }
        __syncthreads();   // Dstage free before next row
    }
}

// ---------------------------------------------------------------------------
extern "C" void kernel_launch(void* const* d_in, const int* in_sizes, int n_in,
                              void* d_out, int out_size) {
    const float* x    = (const float*)d_in[0];
    const float* w    = (const float*)d_in[1];
    const float* bias = (const float*)d_in[2];
    const int*   cin  = (const int*)d_in[3];
    const int*   cout = (const int*)d_in[4];
    int K = in_sizes[3];
    int B = in_sizes[0] / (64 * 192 * 192);

    cudaFuncSetAttribute(conv_mma, cudaFuncAttributeMaxDynamicSharedMemorySize,
                         SMEM_TOTAL);

    k_zero<<<(64 * 9 * 64 + 1023) / 1024, 1024>>>();
    k_scatter<<<(K + 255) / 256, 256>>>(w, cin, cout, K);
    k_buildB<<<(18432 + 255) / 256, 256>>>();
    dim3 tg(192, B);
    k_transpose<<<tg, 256>>>(x);
    dim3 grid(3, 19, B);
    conv_mma<<<grid, 256, SMEM_TOTAL>>>(bias, (float*)d_out);
}